// round 1
// baseline (speedup 1.0000x reference)
#include <cuda_runtime.h>

// BiAlignLayer collapses analytically:
//   mean_l(output_i) = mean(i) - mean(j)   (softmax over axis=1 column-sums to 1)
//   mean_m(output_j) = mean(j) - mean(i)   (softmax over last axis row-sums to 1)
//   out = 0.5*(relu(x@W + b) + relu(-x@W + b)),  x = mean(i) - mean(j)
// => pure streaming reduction over i,j (134 MB) + tiny GEMM. HBM-bound.

#define BATCH   32
#define LSEQ    1024
#define DDIM    512
#define NNDIM   512
#define CHUNKS  32
#define ROWS    (LSEQ / CHUNKS)   // 32 rows per chunk

// Scratch: per-(b,chunk) partial sums of (i - j). Fully overwritten every launch.
__device__ float g_partial[BATCH * CHUNKS * DDIM];

// -------- Stage 1: streaming reduction ---------------------------------
// grid = (CHUNKS, BATCH), 128 threads. Each block reads a contiguous 64KB slab
// of i and of j (32 rows x 512 floats) and writes one 2KB partial row.
__global__ __launch_bounds__(128) void reduce_ij_kernel(
    const float* __restrict__ gi, const float* __restrict__ gj)
{
    const int b = blockIdx.y;
    const int c = blockIdx.x;
    const int t = threadIdx.x;                 // 0..127, covers D via float4

    const size_t base = ((size_t)b * LSEQ + (size_t)c * ROWS) * DDIM;
    const float4* pi = reinterpret_cast<const float4*>(gi + base) + t;
    const float4* pj = reinterpret_cast<const float4*>(gj + base) + t;

    float4 acc = make_float4(0.f, 0.f, 0.f, 0.f);
    #pragma unroll 8
    for (int r = 0; r < ROWS; ++r) {
        float4 vi = pi[(size_t)r * (DDIM / 4)];
        float4 vj = pj[(size_t)r * (DDIM / 4)];
        acc.x += vi.x - vj.x;
        acc.y += vi.y - vj.y;
        acc.z += vi.z - vj.z;
        acc.w += vi.w - vj.w;
    }
    float4* out4 = reinterpret_cast<float4*>(g_partial) +
                   (size_t)(b * CHUNKS + c) * (DDIM / 4) + t;
    *out4 = acc;
}

// -------- Stage 2: finish reduction + tiny GEMM + symmetric relu -------
// grid = (NNDIM/128, BATCH), 128 threads; thread -> one output column n.
__global__ __launch_bounds__(128) void agg_kernel(
    const float* __restrict__ W,      // [D, NN] row-major
    const float* __restrict__ bias,   // [NN]
    float* __restrict__ out)          // [B, NN]
{
    const int b = blockIdx.y;
    const int n = blockIdx.x * 128 + threadIdx.x;

    __shared__ float xs[DDIM];

    // Finish chunk reduction: x[d] = (1/L) * sum_c partial[b][c][d]
    for (int d = threadIdx.x; d < DDIM; d += 128) {
        float s = 0.f;
        const float* p = g_partial + (size_t)b * CHUNKS * DDIM + d;
        #pragma unroll
        for (int c = 0; c < CHUNKS; ++c) s += p[(size_t)c * DDIM];
        xs[d] = s * (1.0f / (float)LSEQ);
    }
    __syncthreads();

    // y[n] = sum_d x[d] * W[d][n]  (coalesced across threads; W is L2-resident)
    float y = 0.f;
    #pragma unroll 8
    for (int d = 0; d < DDIM; ++d) {
        y = fmaf(xs[d], W[(size_t)d * NNDIM + n], y);
    }

    const float bb = bias[n];
    out[(size_t)b * NNDIM + n] =
        0.5f * (fmaxf(y + bb, 0.f) + fmaxf(bb - y, 0.f));
}

extern "C" void kernel_launch(void* const* d_in, const int* in_sizes, int n_in,
                              void* d_out, int out_size)
{
    const float* gi   = (const float*)d_in[0];   // i     [32,1024,512]
    const float* gj   = (const float*)d_in[1];   // j     [32,1024,512]
    const float* W    = (const float*)d_in[2];   // W_agg [512,512]
    const float* bias = (const float*)d_in[3];   // b_agg [512]
    float* out        = (float*)d_out;           // [32,512]

    (void)in_sizes; (void)n_in; (void)out_size;

    dim3 g1(CHUNKS, BATCH);
    reduce_ij_kernel<<<g1, 128>>>(gi, gj);

    dim3 g2(NNDIM / 128, BATCH);
    agg_kernel<<<g2, 128>>>(W, bias, out);
}

// round 4
// speedup vs baseline: 1.6421x; 1.6421x over previous
#include <cuda_runtime.h>

// BiAlignLayer collapses analytically:
//   mean_l(output_i) = mean(i) - mean(j);  mean_m(output_j) = -(that)
//   out = 0.5*(relu(xW + b) + relu(b - xW)),  x = mean(i) - mean(j)
// K1: HBM-bound streaming reduce of (i - j)  (134 MB, roofline ~20us)
// K2: finalize x[b][d]  (tiny)
// K3: [32,512]x[512,512] GEMM + symmetric-relu epilogue, 4-way D-split
//     per output to kill the serial-FMA/L2-latency exposure seen in R1.

#define BATCH   32
#define LSEQ    1024
#define DDIM    512
#define NNDIM   512
#define CHUNKS  32
#define ROWS    (LSEQ / CHUNKS)   // 32

__device__ float g_partial[BATCH * CHUNKS * DDIM];  // fully rewritten each launch
__device__ float g_x[BATCH * DDIM];                 // fully rewritten each launch

// -------- K1: streaming reduction (HBM-bound) --------------------------
__global__ __launch_bounds__(128) void reduce_ij_kernel(
    const float* __restrict__ gi, const float* __restrict__ gj)
{
    const int b = blockIdx.y;
    const int c = blockIdx.x;
    const int t = threadIdx.x;

    const size_t base = ((size_t)b * LSEQ + (size_t)c * ROWS) * DDIM;
    const float4* pi = reinterpret_cast<const float4*>(gi + base) + t;
    const float4* pj = reinterpret_cast<const float4*>(gj + base) + t;

    float4 acc = make_float4(0.f, 0.f, 0.f, 0.f);
    #pragma unroll 8
    for (int r = 0; r < ROWS; ++r) {
        float4 vi = pi[(size_t)r * (DDIM / 4)];
        float4 vj = pj[(size_t)r * (DDIM / 4)];
        acc.x += vi.x - vj.x;
        acc.y += vi.y - vj.y;
        acc.z += vi.z - vj.z;
        acc.w += vi.w - vj.w;
    }
    float4* out4 = reinterpret_cast<float4*>(g_partial) +
                   (size_t)(b * CHUNKS + c) * (DDIM / 4) + t;
    *out4 = acc;
}

// -------- K2: finalize x[b][d] = sum_c partial / L ---------------------
// grid = BATCH, 128 threads. ~2MB of L2-resident reads total.
__global__ __launch_bounds__(128) void finalize_x_kernel()
{
    const int b = blockIdx.x;
    for (int d = threadIdx.x; d < DDIM; d += 128) {
        const float* p = g_partial + (size_t)b * CHUNKS * DDIM + d;
        float s = 0.f;
        #pragma unroll
        for (int c = 0; c < CHUNKS; ++c) s += p[(size_t)c * DDIM];
        g_x[b * DDIM + d] = s * (1.0f / (float)LSEQ);
    }
}

// -------- K3: tiny GEMM + epilogue, 4-way D-split ----------------------
// grid = (NN/128, BATCH), 512 threads.
// Thread t: n = nblk*128 + (t&127), d-slice = t>>7 (128 d's each).
// Warps have constant d-slice, consecutive n -> coalesced W loads (L2-hit).
__global__ __launch_bounds__(512) void agg_kernel(
    const float* __restrict__ W,      // [D, NN] row-major
    const float* __restrict__ bias,   // [NN]
    float* __restrict__ out)          // [B, NN]
{
    const int b    = blockIdx.y;
    const int t    = threadIdx.x;
    const int nloc = t & 127;
    const int ds   = t >> 7;                       // 0..3
    const int n    = blockIdx.x * 128 + nloc;

    __shared__ float xs[DDIM];
    __shared__ float red[4][128];

    // cooperative x load into smem (one float per thread)
    xs[t] = g_x[b * DDIM + t];
    __syncthreads();

    const int d0 = ds * 128;
    const float* Wp = W + (size_t)d0 * NNDIM + n;

    float y = 0.f;
    #pragma unroll 16
    for (int k = 0; k < 128; ++k) {
        y = fmaf(xs[d0 + k], Wp[(size_t)k * NNDIM], y);
    }
    red[ds][nloc] = y;
    __syncthreads();

    if (ds == 0) {
        float ysum = red[0][nloc] + red[1][nloc] + red[2][nloc] + red[3][nloc];
        const float bb = bias[n];
        out[(size_t)b * NNDIM + n] =
            0.5f * (fmaxf(ysum + bb, 0.f) + fmaxf(bb - ysum, 0.f));
    }
}

extern "C" void kernel_launch(void* const* d_in, const int* in_sizes, int n_in,
                              void* d_out, int out_size)
{
    const float* gi   = (const float*)d_in[0];   // i     [32,1024,512]
    const float* gj   = (const float*)d_in[1];   // j     [32,1024,512]
    const float* W    = (const float*)d_in[2];   // W_agg [512,512]
    const float* bias = (const float*)d_in[3];   // b_agg [512]
    float* out        = (float*)d_out;           // [32,512]

    (void)in_sizes; (void)n_in; (void)out_size;

    dim3 g1(CHUNKS, BATCH);
    reduce_ij_kernel<<<g1, 128>>>(gi, gj);

    finalize_x_kernel<<<BATCH, 128>>>();

    dim3 g3(NNDIM / 128, BATCH);
    agg_kernel<<<g3, 512>>>(W, bias, out);
}